// round 4
// baseline (speedup 1.0000x reference)
#include <cuda_runtime.h>
#include <cuda_bf16.h>

#define FULL_MASK 0xFFFFFFFFu

// 4 lanes per row, 8 rows per "tile", 2 tiles (16 contiguous rows) per warp.
// Pipeline: chunk-0 nidx loads and score gathers for BOTH tiles are issued
// before any decision, so two memory round trips overlap per warp.
// Chunk 0 covers columns 1-4 (column 0 is self: never gathered) and decides
// ~80% of rows in one shot; stragglers scan remaining columns in chunks of 4
// with per-group early exit. Outputs use streaming stores (__stcs) so the
// 512MB write stream does not evict the 4MB score array from L2.
__global__ void __launch_bounds__(256)
dgb_kernel(const float4* __restrict__ dist4,
           const int*    __restrict__ nidx,
           const float*  __restrict__ score,
           float4* __restrict__ dist_out4,
           float4* __restrict__ nidx_out4,
           long long V)
{
    long long warp_id = ((long long)blockIdx.x * blockDim.x + threadIdx.x) >> 5;
    int lane = threadIdx.x & 31;
    int g = lane >> 2;                      // row group within tile: 0..7
    int l = lane & 3;                       // lane within group: 0..3
    unsigned grpmask = 0xFu << (g << 2);

    long long r[2];
    r[0] = warp_id * 16 + g;                // tile 0 rows
    r[1] = r[0] + 8;                        // tile 1 rows
    bool valid[2] = { r[0] < V, r[1] < V };

    // ---- phase A: issue sv + chunk-0 nidx loads for both tiles ----
    float sv[2];
    int ni0[2];
    #pragma unroll
    for (int t = 0; t < 2; ++t) {
        sv[t]  = valid[t] ? __ldg(score + r[t]) : 3.0f;      // >1: never beaten
        ni0[t] = valid[t] ? __ldg(nidx + r[t] * 64 + 1 + l) : -1;  // cols 1..4
    }

    // ---- phase B: chunk-0 score gathers for both tiles ----
    bool beat[2];
    #pragma unroll
    for (int t = 0; t < 2; ++t)
        beat[t] = (ni0[t] >= 0) && (__ldg(score + ni0[t]) > sv[t]);

    // ---- phase C: decide; stragglers scan chunks of 4 with early exit ----
    bool cond[2];
    #pragma unroll
    for (int t = 0; t < 2; ++t) {
        cond[t] = __any_sync(grpmask, beat[t]);
        if (valid[t] && !cond[t]) {          // group-uniform condition
            const int* nrow = nidx + r[t] * 64;
            #pragma unroll 1
            for (int j = 1; j < 16; ++j) {
                int col = (j << 2) + 1 + l;  // 5..63 (+guard for 64)
                bool b = false;
                if (col < 64) {
                    int ni = __ldg(nrow + col);
                    if (ni >= 0)
                        b = __ldg(score + ni) > sv[t];   // strict: diff < 0
                }
                if (__any_sync(grpmask, b)) { cond[t] = true; break; }
            }
        }
    }

    // Publish cond bits for all rows (bit of group g at lane g*4).
    unsigned bal[2];
    bal[0] = __ballot_sync(FULL_MASK, cond[0]);
    bal[1] = __ballot_sync(FULL_MASK, cond[1]);

    // ---- write phase: contiguous streaming, 8 rows per tile ----
    const int4* nidx4 = (const int4*)nidx;
    #pragma unroll
    for (int t = 0; t < 2; ++t) {
        long long wr0 = warp_id * 16 + t * 8;
        long long gbase = wr0 * 16;          // float4 index of tile start
        #pragma unroll
        for (int q = 0; q < 4; ++q) {
            int vec = q * 32 + lane;         // 0..127 within tile
            int row_local = vec >> 4;        // 0..7
            int within = vec & 15;           // float4 within row
            long long rr = wr0 + row_local;
            if (rr >= V) continue;
            long long idx = gbase + vec;

            bool c = (bal[t] >> (row_local << 2)) & 1u;

            float4 dv, nv;
            if (c) {
                dv = make_float4(0.f, 0.f, 0.f, 0.f);
                nv = make_float4(-1.f, -1.f, -1.f, -1.f);
                if (within == 0) nv.x = (float)rr;
            } else {
                dv = __ldcs(dist4 + idx);
                int4 ni = __ldcs(nidx4 + idx);
                nv = make_float4((float)ni.x, (float)ni.y,
                                 (float)ni.z, (float)ni.w);
            }
            __stcs(dist_out4 + idx, dv);
            __stcs(nidx_out4 + idx, nv);
        }
    }
}

extern "C" void kernel_launch(void* const* d_in, const int* in_sizes, int n_in,
                              void* d_out, int out_size)
{
    const float* dist  = (const float*)d_in[0];   // [V, 64] f32
    const int*   nidx  = (const int*)d_in[1];     // [V, 64] i32
    const float* score = (const float*)d_in[2];   // [V, 1]  f32

    long long V = in_sizes[2];                    // score element count == V

    float* out      = (float*)d_out;
    float* dist_out = out;                        // first V*64 floats
    float* nidx_out = out + V * 64;               // second V*64 (ints as f32)

    // 16 rows per warp -> V*2 threads
    long long total_threads = V * 2;
    int threads = 256;
    long long blocks = (total_threads + threads - 1) / threads;

    dgb_kernel<<<(unsigned int)blocks, threads>>>(
        (const float4*)dist, nidx, score,
        (float4*)dist_out, (float4*)nidx_out, V);
}

// round 5
// speedup vs baseline: 1.1031x; 1.1031x over previous
#include <cuda_runtime.h>
#include <cuda_bf16.h>

#define FULL_MASK 0xFFFFFFFFu

// 4 lanes per row, 8 rows per warp (R3 shape — occupancy-friendly).
// Scan columns 1..63 in chunks of 4 with per-group early exit; the next
// chunk's nidx load is prefetched while the current chunk's gathers are in
// flight, overlapping the two dependent memory latencies. Column 0 (self)
// is never gathered. Output stores are streaming (__stcs) to keep the 4MB
// score array resident in L2 under the 512MB write stream.
__global__ void __launch_bounds__(256)
dgb_kernel(const float4* __restrict__ dist4,
           const int*    __restrict__ nidx,
           const float*  __restrict__ score,
           float4* __restrict__ dist_out4,
           float4* __restrict__ nidx_out4,
           long long V)
{
    long long warp_id = ((long long)blockIdx.x * blockDim.x + threadIdx.x) >> 5;
    int lane = threadIdx.x & 31;
    int g = lane >> 2;                 // row group within warp: 0..7
    int l = lane & 3;                  // lane within group: 0..3
    unsigned grpmask = 0xFu << (g << 2);

    long long row = warp_id * 8 + g;
    bool valid = row < V;
    long long srow = valid ? row : 0;  // safe row for loads when past tail

    float sv = valid ? __ldg(score + row) : 3.0f;   // >1 => never beaten
    const int* nrow = nidx + srow * 64;

    // ---- early-exit scan with next-chunk nidx prefetch ----
    bool cond = false;                 // true => some neighbour beats sv
    int col = 1 + l;                   // chunk 0: columns 1..4 (skip self)
    int ni  = __ldg(nrow + col);

    #pragma unroll 1
    for (int j = 0; j < 16; ++j) {
        // prefetch next chunk's nidx (independent of this chunk's gather)
        int next_col = col + 4;
        int ni_next = (next_col < 64) ? __ldg(nrow + next_col) : -1;

        bool beat = false;
        if (col < 64 && ni >= 0)
            beat = __ldg(score + ni) > sv;          // strict: diff < 0

        if (__any_sync(grpmask, beat)) { cond = true; break; }

        ni  = ni_next;
        col = next_col;
    }

    // Publish cond bits for all 8 rows of this warp (bit at lane g*4).
    unsigned bal = __ballot_sync(FULL_MASK, cond);

    // ---- write phase: contiguous streaming over the warp's 8 rows ----
    long long warp_row0 = warp_id * 8;
    long long gbase = warp_row0 * 16;  // float4 index of region start
    const int4* nidx4 = (const int4*)nidx;

    #pragma unroll
    for (int t = 0; t < 4; ++t) {
        int vec = t * 32 + lane;       // 0..127 within warp region
        int row_local = vec >> 4;      // 0..7
        int within = vec & 15;         // float4 within row
        long long rr = warp_row0 + row_local;
        if (rr >= V) continue;
        long long idx = gbase + vec;

        bool c = (bal >> (row_local << 2)) & 1u;

        float4 dv, nv;
        if (c) {
            dv = make_float4(0.f, 0.f, 0.f, 0.f);
            nv = make_float4(-1.f, -1.f, -1.f, -1.f);
            if (within == 0) nv.x = (float)rr;
        } else {
            dv = __ldg(dist4 + idx);
            int4 niv = __ldg(nidx4 + idx);
            nv = make_float4((float)niv.x, (float)niv.y,
                             (float)niv.z, (float)niv.w);
        }
        __stcs(dist_out4 + idx, dv);
        __stcs(nidx_out4 + idx, nv);
    }
}

extern "C" void kernel_launch(void* const* d_in, const int* in_sizes, int n_in,
                              void* d_out, int out_size)
{
    const float* dist  = (const float*)d_in[0];   // [V, 64] f32
    const int*   nidx  = (const int*)d_in[1];     // [V, 64] i32
    const float* score = (const float*)d_in[2];   // [V, 1]  f32

    long long V = in_sizes[2];                    // score element count == V

    float* out      = (float*)d_out;
    float* dist_out = out;                        // first V*64 floats
    float* nidx_out = out + V * 64;               // second V*64 (ints as f32)

    // 4 lanes per row -> V*4 threads
    long long total_threads = V * 4;
    int threads = 256;
    long long blocks = (total_threads + threads - 1) / threads;

    dgb_kernel<<<(unsigned int)blocks, threads>>>(
        (const float4*)dist, nidx, score,
        (float4*)dist_out, (float4*)nidx_out, V);
}